// round 1
// baseline (speedup 1.0000x reference)
#include <cuda_runtime.h>

#define N_NODES 50000
#define N_EDGES 640000
#define D 128

// Scratch for per-node projections (no cudaMalloc allowed).
__device__ float g_a[N_NODES];   // h[n] . w_src
__device__ float g_b[N_NODES];   // h[n] . w_dst

__device__ __forceinline__ float warp_reduce(float v) {
    v += __shfl_xor_sync(0xFFFFFFFFu, v, 16);
    v += __shfl_xor_sync(0xFFFFFFFFu, v, 8);
    v += __shfl_xor_sync(0xFFFFFFFFu, v, 4);
    v += __shfl_xor_sync(0xFFFFFFFFu, v, 2);
    v += __shfl_xor_sync(0xFFFFFFFFu, v, 1);
    return v;
}

// One warp per node: a[n] = h[n].w_src, b[n] = h[n].w_dst
__global__ void node_proj_kernel(const float* __restrict__ h,
                                 const float* __restrict__ weight) {
    int gwarp = (blockIdx.x * blockDim.x + threadIdx.x) >> 5;
    int lane  = threadIdx.x & 31;
    if (gwarp >= N_NODES) return;

    const float4* h4 = reinterpret_cast<const float4*>(h) + (size_t)gwarp * 32 + lane;
    float4 hv = *h4;

    const float4* w4 = reinterpret_cast<const float4*>(weight);
    float4 ws = __ldg(w4 + lane);        // weight[0,   0:128)
    float4 wd = __ldg(w4 + 32 + lane);   // weight[0, 128:256)

    float pa = hv.x * ws.x + hv.y * ws.y + hv.z * ws.z + hv.w * ws.w;
    float pb = hv.x * wd.x + hv.y * wd.y + hv.z * wd.z + hv.w * wd.w;

    pa = warp_reduce(pa);
    pb = warp_reduce(pb);

    if (lane == 0) {
        g_a[gwarp] = pa;
        g_b[gwarp] = pb;
    }
}

// One warp per edge: out[i] = a[src[i]] + b[dst[i]] + e[i].w_e + bias
__global__ void edge_kernel(const float* __restrict__ e,
                            const int*   __restrict__ src,
                            const int*   __restrict__ dst,
                            const float* __restrict__ weight,
                            const float* __restrict__ bias,
                            float*       __restrict__ out) {
    int gwarp = (blockIdx.x * blockDim.x + threadIdx.x) >> 5;
    int lane  = threadIdx.x & 31;
    if (gwarp >= N_EDGES) return;

    // Streaming read of e (no reuse) — evict-first.
    const float4* e4 = reinterpret_cast<const float4*>(e) + (size_t)gwarp * 32 + lane;
    float4 ev = __ldcs(e4);

    const float4* w4 = reinterpret_cast<const float4*>(weight);
    float4 we = __ldg(w4 + 64 + lane);   // weight[0, 256:384)

    float p = ev.x * we.x + ev.y * we.y + ev.z * we.z + ev.w * we.w;
    p = warp_reduce(p);

    if (lane == 0) {
        int s = src[gwarp];
        int d = dst[gwarp];
        out[gwarp] = p + g_a[s] + g_b[d] + __ldg(bias);
    }
}

extern "C" void kernel_launch(void* const* d_in, const int* in_sizes, int n_in,
                              void* d_out, int out_size) {
    const float* h      = (const float*)d_in[0];
    const float* e      = (const float*)d_in[1];
    const int*   src    = (const int*)d_in[2];
    const int*   dst    = (const int*)d_in[3];
    const float* weight = (const float*)d_in[4];
    const float* bias   = (const float*)d_in[5];
    float*       out    = (float*)d_out;

    // Kernel 1: 50000 warps, 8 warps/block -> 6250 blocks
    {
        int threads = 256;
        int warps_per_block = threads / 32;
        int blocks = (N_NODES + warps_per_block - 1) / warps_per_block;
        node_proj_kernel<<<blocks, threads>>>(h, weight);
    }

    // Kernel 2: 640000 warps, 8 warps/block -> 80000 blocks
    {
        int threads = 256;
        int warps_per_block = threads / 32;
        int blocks = (N_EDGES + warps_per_block - 1) / warps_per_block;
        edge_kernel<<<blocks, threads>>>(e, src, dst, weight, bias, out);
    }
}

// round 2
// speedup vs baseline: 1.5906x; 1.5906x over previous
#include <cuda_runtime.h>

#define N_NODES 50000
#define N_EDGES 640000
#define D 128

#define EPW 8   // edges per warp (edge kernel)
#define NPW 4   // nodes per warp (node kernel)

// Scratch for per-node projections (no cudaMalloc allowed).
__device__ float g_a[N_NODES];   // h[n] . w_src
__device__ float g_b[N_NODES];   // h[n] . w_dst

// One warp handles NPW nodes: a[n] = h[n].w_src, b[n] = h[n].w_dst
__global__ __launch_bounds__(256) void node_proj_kernel(
        const float* __restrict__ h,
        const float* __restrict__ weight) {
    int gwarp = (blockIdx.x * blockDim.x + threadIdx.x) >> 5;
    int lane  = threadIdx.x & 31;
    int base  = gwarp * NPW;
    if (base >= N_NODES) return;

    const float4* w4 = reinterpret_cast<const float4*>(weight);
    float4 ws = __ldg(w4 + lane);        // weight[0,   0:128)
    float4 wd = __ldg(w4 + 32 + lane);   // weight[0, 128:256)

    float pa[NPW], pb[NPW];
    const float4* h4 = reinterpret_cast<const float4*>(h);

    // Issue all loads first (MLP), guarded for tail.
    float4 hv[NPW];
    #pragma unroll
    for (int k = 0; k < NPW; k++) {
        int n = base + k;
        hv[k] = (n < N_NODES) ? __ldcs(h4 + (size_t)n * 32 + lane)
                              : make_float4(0.f, 0.f, 0.f, 0.f);
    }
    #pragma unroll
    for (int k = 0; k < NPW; k++) {
        pa[k] = hv[k].x * ws.x + hv[k].y * ws.y + hv[k].z * ws.z + hv[k].w * ws.w;
        pb[k] = hv[k].x * wd.x + hv[k].y * wd.y + hv[k].z * wd.z + hv[k].w * wd.w;
    }

    // Butterfly reduce all 2*NPW independent partials together.
    #pragma unroll
    for (int off = 16; off >= 1; off >>= 1) {
        #pragma unroll
        for (int k = 0; k < NPW; k++) {
            pa[k] += __shfl_xor_sync(0xFFFFFFFFu, pa[k], off);
            pb[k] += __shfl_xor_sync(0xFFFFFFFFu, pb[k], off);
        }
    }

    // Lanes 0..NPW-1 each store one node's pair.
    if (lane < NPW && base + lane < N_NODES) {
        // After full butterfly, every lane holds the complete sum of every k.
        // Select this lane's value via shfl from lane 0 (all lanes identical),
        // so just index locally:
        float va, vb;
        switch (lane) {
            case 0: va = pa[0]; vb = pb[0]; break;
            case 1: va = pa[1]; vb = pb[1]; break;
            case 2: va = pa[2]; vb = pb[2]; break;
            default: va = pa[3]; vb = pb[3]; break;
        }
        g_a[base + lane] = va;
        g_b[base + lane] = vb;
    }
}

// One warp handles EPW edges: out[i] = a[src[i]] + b[dst[i]] + e[i].w_e + bias
__global__ __launch_bounds__(256) void edge_kernel(
        const float* __restrict__ e,
        const int*   __restrict__ src,
        const int*   __restrict__ dst,
        const float* __restrict__ weight,
        const float* __restrict__ bias,
        float*       __restrict__ out) {
    int gwarp = (blockIdx.x * blockDim.x + threadIdx.x) >> 5;
    int lane  = threadIdx.x & 31;
    int base  = gwarp * EPW;
    if (base >= N_EDGES) return;

    const float4* w4 = reinterpret_cast<const float4*>(weight);
    float4 we = __ldg(w4 + 64 + lane);   // weight[0, 256:384)

    const float4* e4 = reinterpret_cast<const float4*>(e);

    // Issue all EPW streaming loads up front -> high MLP.
    float4 ev[EPW];
    #pragma unroll
    for (int k = 0; k < EPW; k++) {
        ev[k] = __ldcs(e4 + (size_t)(base + k) * 32 + lane);
    }

    float p[EPW];
    #pragma unroll
    for (int k = 0; k < EPW; k++) {
        p[k] = ev[k].x * we.x + ev[k].y * we.y + ev[k].z * we.z + ev[k].w * we.w;
    }

    #pragma unroll
    for (int off = 16; off >= 1; off >>= 1) {
        #pragma unroll
        for (int k = 0; k < EPW; k++) {
            p[k] += __shfl_xor_sync(0xFFFFFFFFu, p[k], off);
        }
    }

    // Lanes 0..EPW-1 each finalize one edge (parallel L2 gathers + stores).
    if (lane < EPW) {
        int edge = base + lane;
        // Every lane holds every fully-reduced p[k]; pick p[lane].
        float pe;
        switch (lane) {
            case 0: pe = p[0]; break;
            case 1: pe = p[1]; break;
            case 2: pe = p[2]; break;
            case 3: pe = p[3]; break;
            case 4: pe = p[4]; break;
            case 5: pe = p[5]; break;
            case 6: pe = p[6]; break;
            default: pe = p[7]; break;
        }
        int s = src[edge];
        int d = dst[edge];
        out[edge] = pe + g_a[s] + g_b[d] + __ldg(bias);
    }
}

extern "C" void kernel_launch(void* const* d_in, const int* in_sizes, int n_in,
                              void* d_out, int out_size) {
    const float* h      = (const float*)d_in[0];
    const float* e      = (const float*)d_in[1];
    const int*   src    = (const int*)d_in[2];
    const int*   dst    = (const int*)d_in[3];
    const float* weight = (const float*)d_in[4];
    const float* bias   = (const float*)d_in[5];
    float*       out    = (float*)d_out;

    // Node kernel: 50000 nodes / 4 per warp = 12500 warps; 8 warps/block.
    {
        int warps  = (N_NODES + NPW - 1) / NPW;
        int blocks = (warps + 7) / 8;
        node_proj_kernel<<<blocks, 256>>>(h, weight);
    }

    // Edge kernel: 640000 edges / 8 per warp = 80000 warps; 8 warps/block.
    {
        int warps  = (N_EDGES + EPW - 1) / EPW;
        int blocks = (warps + 7) / 8;
        edge_kernel<<<blocks, 256>>>(e, src, dst, weight, bias, out);
    }
}